// round 12
// baseline (speedup 1.0000x reference)
#include <cuda_runtime.h>
#include <cstdint>

// CRF loss, bidirectional scaled forward algorithm, ONE WARP PER DIRECTION.
// CTA = 64 threads per batch row: warp 0 = alpha forward (t=0..m), warp 1 =
// beta backward (t=len-1..m); Z = sum_i alpha_m[i]*beta_m[i].
// Thread l owns adjacent columns (2l, 2l+1): 2 x 26 fma.rn.f32x2 against 52
// pre-packed E registers, P exchanged via smem with only __syncwarp() --
// no block/named barriers anywhere in the recurrence.
// Exact pow-2 rescaling per step from the exponent of max(P[1..3]).

constexpr int TT = 50;
constexpr int LL = 256;
constexpr int NTH = 64;
constexpr int STARTT = TT - 2;
constexpr int STOPT  = TT - 1;

#define LOG2E 1.4426950408889634f
#define LN2F  0.6931471805599453f

__device__ float    g_partial[1024];
__device__ unsigned g_done = 0;

__device__ __forceinline__ float ex2(float x) {
    float r;
    asm("ex2.approx.ftz.f32 %0, %1;" : "=f"(r) : "f"(x));
    return r;
}

#define PACK2(d, lo, hi) \
    asm("mov.b64 %0, {%1, %2};" : "=l"(d) : "f"(lo), "f"(hi))
#define UNPACK2(lo, hi, s) \
    asm("mov.b64 {%0, %1}, %2;" : "=f"(lo), "=f"(hi) : "l"(s))
#define FFMA2(d, a, b, c) \
    asm("fma.rn.f32x2 %0, %1, %2, %3;" : "=l"(d) : "l"(a), "l"(b), "l"(c))
#define FMUL2(d, a, b) \
    asm("mul.rn.f32x2 %0, %1, %2;" : "=l"(d) : "l"(a), "l"(b))
#define FADD2(d, a, b) \
    asm("add.rn.f32x2 %0, %1, %2;" : "=l"(d) : "l"(a), "l"(b))
#define LDS_V2U64(q0, q1, addr) \
    asm volatile("ld.shared.v2.u64 {%0, %1}, [%2];" \
                 : "=l"(q0), "=l"(q1) : "r"(addr))
#define STS_U64(addr, v) \
    asm volatile("st.shared.u64 [%0], %1;" :: "r"(addr), "l"(v))

__device__ __forceinline__ float blockSum64(float v, volatile float* red) {
#pragma unroll
    for (int o = 16; o; o >>= 1) v += __shfl_xor_sync(0xffffffffu, v, o);
    if ((threadIdx.x & 31) == 0) red[threadIdx.x >> 5] = v;
    __syncthreads();
    v = red[0] + red[1];
    __syncthreads();
    return v;
}

__global__ void __launch_bounds__(NTH, 1)
crf_kernel(const float* __restrict__ feats, const float* __restrict__ trans,
           const int* __restrict__ tags, const int* __restrict__ mask,
           float* __restrict__ out) {
    __shared__ __align__(16) float Ab[2][64];   // alpha ping-pong
    __shared__ __align__(16) float Bb[2][64];   // beta  ping-pong
    __shared__ float red[2];
    __shared__ int s_len, s_kf, s_kb;
    __shared__ unsigned s_rank;

    const int b    = blockIdx.x;
    const int tid  = threadIdx.x;
    const bool isF = (tid < 32);        // warp 0 forward, warp 1 backward
    const int lane = tid & 31;
    const int c0   = 2 * lane;          // my two adjacent columns
    const int c1   = 2 * lane + 1;
    const bool v0  = (c0 < TT);
    const bool v1  = (c1 < TT);
    const int c0c  = v0 ? c0 : (TT - 1);
    const int c0f  = min(c0, TT - 2);   // even, for aligned float2 feats loads

    if (tid == 0) s_len = 0;
    __syncthreads();

    // ---- sequence length (mask is a 0/1 prefix) ----
    {
        const int4* m4 = (const int4*)(mask + (size_t)b * LL);
        int4 v = m4[tid];
        int c = (v.x != 0) + (v.y != 0) + (v.z != 0) + (v.w != 0);
#pragma unroll
        for (int o = 16; o; o >>= 1) c += __shfl_xor_sync(0xffffffffu, c, o);
        if ((tid & 31) == 0) atomicAdd(&s_len, c);
    }

    // ---- E packed: EA[x]/EB[x] = (E[2x], E[2x+1]) for columns c0 / c1
    //      forward:  E[i][c] = exp(trans[i][c])  (stride TT)
    //      backward: E[i][c] = exp(trans[c][i])  (stride 1) ----
    uint64_t EA[26], EB[26];
    {
        const float* ta = isF ? (trans + c0)      : (trans + c0 * TT);
        const float* tb = isF ? (trans + (v1 ? c1 : c0c))
                              : (trans + (v1 ? c1 : c0c) * TT);
        const int    ts = isF ? TT : 1;
#pragma unroll
        for (int x = 0; x < 26; x++) {
            int i0 = 2 * x, i1 = 2 * x + 1;
            float ea0 = (v0 && i0 < TT) ? ex2(ta[i0 * ts] * LOG2E) : 0.f;
            float ea1 = (v0 && i1 < TT) ? ex2(ta[i1 * ts] * LOG2E) : 0.f;
            float eb0 = (v1 && i0 < TT) ? ex2(tb[i0 * ts] * LOG2E) : 0.f;
            float eb1 = (v1 && i1 < TT) ? ex2(tb[i1 * ts] * LOG2E) : 0.f;
            PACK2(EA[x], ea0, ea1);
            PACK2(EB[x], eb0, eb1);
        }
    }

    const float* fb = feats + (size_t)b * LL * TT;
    const float s0   = trans[STARTT * TT + 1];
    const float tref = trans[1 * TT + STOPT];
    const float C2f  = s0 * LOG2E;

    __syncthreads();
    const int len = s_len;
    const int nf  = (len - 1) >> 1;        // forward steps
    const int nb  = (len - 1) - nf;        // backward steps (>= nf)

    // ---- inits: write my two columns of buffer 0 (zeros for pads) ----
    if (isF) {
        float p0 = v0 ? ex2((fb[c0c] + trans[STARTT * TT + c0c] - s0) * LOG2E) : 0.f;
        float p1 = v1 ? ex2((fb[c1] + trans[STARTT * TT + c1] - s0) * LOG2E) : 0.f;
        Ab[0][c0] = p0; Ab[0][c1] = p1;
    } else {
        float w0 = v0 ? ex2((trans[c0c * TT + STOPT] - tref) * LOG2E) : 0.f;
        float w1 = v1 ? ex2((trans[c1 * TT + STOPT] - tref) * LOG2E) : 0.f;
        float f0 = 1.f, f1 = 1.f;
        if (nb > 0) {
            float2 fv = *(const float2*)(fb + (len - 1) * TT + c0f);
            f0 = ex2(fv.x * LOG2E); f1 = ex2(fv.y * LOG2E);
        }
        Bb[0][c0] = v0 ? w0 * f0 : 0.f;
        Bb[0][c1] = v1 ? w1 * f1 : 0.f;
    }
    int kacc = 0;

    // ---- distance-2 feats prefetch (clamped, aligned float2) ----
    int r1 = isF ? 1 : len - 2;
    int r2 = isF ? 2 : len - 3;
    r1 = min(max(r1, 0), len - 1);
    r2 = min(max(r2, 0), len - 1);
    float2 fcv = *(const float2*)(fb + r1 * TT + c0f);
    float2 fnv = *(const float2*)(fb + r2 * TT + c0f);

    float* Pc = isF ? Ab[0] : Bb[0];
    float* Pn = isF ? Ab[1] : Bb[1];
    __syncwarp();

    // one step: two packed 52-term dots + exact pow2 rescale + one STS.64
#define CRF_STEP(EFA, EFB)                                                  \
    {                                                                       \
        unsigned sc_ = (unsigned)__cvta_generic_to_shared(Pc);              \
        unsigned sn_ = (unsigned)__cvta_generic_to_shared(Pn) + c0 * 4;     \
        uint64_t q0, q1;                                                    \
        uint64_t aa0, aa1, aa2, aa3, ba0, ba1, ba2, ba3;                    \
        LDS_V2U64(q0, q1, sc_);                                             \
        float pv0, pv1, pv2, pv3;                                           \
        UNPACK2(pv0, pv1, q0);                                              \
        UNPACK2(pv2, pv3, q1);                                              \
        float m_ = fmaxf(fmaxf(pv1, pv2), pv3);                             \
        int   k_ = (__float_as_int(m_) >> 23) - 127;                        \
        float scf = __int_as_float((127 - k_) << 23);                       \
        FMUL2(aa0, q0, EA[0]); FMUL2(ba0, q0, EB[0]);                       \
        FMUL2(aa1, q1, EA[1]); FMUL2(ba1, q1, EB[1]);                       \
        LDS_V2U64(q0, q1, sc_ + 16);                                        \
        FMUL2(aa2, q0, EA[2]); FMUL2(ba2, q0, EB[2]);                       \
        FMUL2(aa3, q1, EA[3]); FMUL2(ba3, q1, EB[3]);                       \
        _Pragma("unroll")                                                   \
        for (int q = 2; q < 13; q++) {                                      \
            LDS_V2U64(q0, q1, sc_ + q * 16);                                \
            FFMA2(aa0, q0, EA[2 * q], aa0);                                 \
            FFMA2(ba0, q0, EB[2 * q], ba0);                                 \
            FFMA2(aa1, q1, EA[2 * q + 1], aa1);                             \
            FFMA2(ba1, q1, EB[2 * q + 1], ba1);                             \
            uint64_t t0 = aa0; aa0 = aa2; aa2 = t0;                         \
            uint64_t t1 = aa1; aa1 = aa3; aa3 = t1;                         \
            uint64_t t2 = ba0; ba0 = ba2; ba2 = t2;                         \
            uint64_t t3 = ba1; ba1 = ba3; ba3 = t3;                         \
        }                                                                   \
        FADD2(aa0, aa0, aa2); FADD2(aa1, aa1, aa3); FADD2(aa0, aa0, aa1);   \
        FADD2(ba0, ba0, ba2); FADD2(ba1, ba1, ba3); FADD2(ba0, ba0, ba1);   \
        float la_, ha_, lb_, hb_;                                           \
        UNPACK2(la_, ha_, aa0);                                             \
        UNPACK2(lb_, hb_, ba0);                                             \
        float ra_ = (la_ + ha_) * (scf * (EFA));                            \
        float rb_ = (lb_ + hb_) * (scf * (EFB));                            \
        uint64_t rp_;                                                       \
        PACK2(rp_, ra_, rb_);                                               \
        STS_U64(sn_, rp_);                                                  \
        kacc += k_;                                                         \
        __syncwarp();                                                       \
        float* _t = Pc; Pc = Pn; Pn = _t;                                   \
    }

    if (isF) {
        for (int s = 1; s <= nf; ++s) {
            float efa = ex2(fcv.x * LOG2E);
            float efb = ex2(fcv.y * LOG2E);
            fcv = fnv;
            int rn = min(s + 2, len - 1);
            fnv = *(const float2*)(fb + rn * TT + c0f);
            CRF_STEP(efa, efb);
        }
    } else {
        for (int s = 1; s < nb; ++s) {
            float efa = ex2(fcv.x * LOG2E);
            float efb = ex2(fcv.y * LOG2E);
            fcv = fnv;
            int rn = max(len - 3 - s, 0);
            fnv = *(const float2*)(fb + rn * TT + c0f);
            CRF_STEP(efa, efb);
        }
        if (nb >= 1) {                  // final step: exclude ef_m
            CRF_STEP(1.0f, 1.0f);
        }
    }
#undef CRF_STEP

    // ---- combine at the midpoint: Z = sum_i alpha_m[i] * beta_m[i] ----
    if (tid == 0)  s_kf = kacc;
    if (tid == 32) s_kb = kacc;
    __syncthreads();
    float z = 0.f;
    if (isF) {
        const float* Bm = Bb[nb & 1];
        z = Pc[c0] * Bm[c0] + Pc[c1] * Bm[c1];
    }
    float sumv = blockSum64(z, red);
    float fwd = (log2f(sumv) + C2f + (float)(s_kf + s_kb)) * LN2F + tref;

    // ---- gold score ----
    const int* tgb = tags + (size_t)b * LL;
    float gl = 0.f;
    for (int t = tid; t < len; t += NTH) {
        int tg = tgb[t];
        int pv = (t == 0) ? STARTT : tgb[t - 1];
        gl += fb[t * TT + tg] + trans[pv * TT + tg];
    }
    float gold = blockSum64(gl, red);

    if (tid == 0) {
        gold += trans[tgb[len - 1] * TT + STOPT];
        g_partial[b] = fwd - gold;
    }

    // ---- fused finalize: last CTA sums all partials (fixed order) ----
    __threadfence();
    if (tid == 0) s_rank = atomicAdd(&g_done, 1u);
    __syncthreads();
    if (s_rank == gridDim.x - 1) {
        const int B = gridDim.x;
        if (tid < 32) {
            float acc = 0.f;
            for (int i = tid; i < B; i += 32) {
                float v;
                asm volatile("ld.global.cg.f32 %0, [%1];" : "=f"(v)
                             : "l"(&g_partial[i]));
                acc += v;
            }
#pragma unroll
            for (int o = 16; o; o >>= 1)
                acc += __shfl_xor_sync(0xffffffffu, acc, o);
            if (tid == 0) {
                *out = acc;
                g_done = 0;   // reset for next graph replay
            }
        }
    }
}

extern "C" void kernel_launch(void* const* d_in, const int* in_sizes, int n_in,
                              void* d_out, int out_size) {
    const float* feats = (const float*)d_in[0];
    const float* trans = (const float*)d_in[1];
    const int*   tags  = (const int*)d_in[2];
    const int*   mask  = (const int*)d_in[3];
    int B = in_sizes[0] / (LL * TT);

    crf_kernel<<<B, NTH>>>(feats, trans, tags, mask, (float*)d_out);
}